// round 1
// baseline (speedup 1.0000x reference)
#include <cuda_runtime.h>

// Problem constants
#define S_LEN 2048
#define B_SZ  128
#define H_SZ  128
#define G_SZ  384   // 3*H
#define C_SZ  10

// Scratch: xp (input projections, reused by both layers) and y0 (layer-0 output seq)
__device__ float g_xp[(size_t)S_LEN * B_SZ * G_SZ];   // [(t*B + b)*3H + g]
__device__ float g_y0[(size_t)S_LEN * B_SZ * H_SZ];   // [(t*B + b)*H + j]

// Packed dual-FP32 FMA: d = a*b + c (elementwise on the two packed floats)
__device__ __forceinline__ unsigned long long fma2(unsigned long long a,
                                                   unsigned long long b,
                                                   unsigned long long c) {
    unsigned long long d;
    asm("fma.rn.f32x2 %0, %1, %2, %3;" : "=l"(d) : "l"(a), "l"(b), "l"(c));
    return d;
}
__device__ __forceinline__ float lo32(unsigned long long v) {
    return __uint_as_float((unsigned)(v & 0xffffffffull));
}
__device__ __forceinline__ float hi32(unsigned long long v) {
    return __uint_as_float((unsigned)(v >> 32));
}

// ---------------------------------------------------------------------------
// Input-projection GEMM:
//   out[(t*B + b)*3H + g] = sum_d in[b*strideB + t*strideT + d] * W[g*H + d] + bias[g]
// Grid: (S_LEN, 2). Each CTA: one t, 64 batch rows, all 384 gate outputs.
// Thread g holds its full W row (128 fp32 = 64 packed u64) in registers;
// the x tile is staged in smem and read via broadcast LDS.128.
// ---------------------------------------------------------------------------
__global__ __launch_bounds__(384, 1)
void gemm_in_kernel(const float* __restrict__ in,
                    const float* __restrict__ W,
                    const float* __restrict__ bias,
                    float* __restrict__ out,
                    long strideB, long strideT)
{
    __shared__ __align__(16) float xs[64 * 128];

    const int t  = blockIdx.x;
    const int b0 = blockIdx.y * 64;
    const int g  = threadIdx.x;

    // Weights for this gate row -> registers (fully unrolled so array stays in regs)
    unsigned long long w[64];
    const unsigned long long* wrow =
        reinterpret_cast<const unsigned long long*>(W + (size_t)g * H_SZ);
#pragma unroll
    for (int i = 0; i < 64; i++) w[i] = wrow[i];
    const float bs = bias[g];

    // Stage x tile [64 rows x 128 d] into smem (float4 loads)
    for (int i = threadIdx.x; i < 64 * 32; i += 384) {
        const int row = i >> 5;
        const int d4  = i & 31;
        const float4 v = *reinterpret_cast<const float4*>(
            in + (size_t)(b0 + row) * strideB + (size_t)t * strideT + (size_t)d4 * 4);
        reinterpret_cast<float4*>(xs)[row * 32 + d4] = v;
    }
    __syncthreads();

    for (int b = 0; b < 64; b++) {
        const ulonglong2* xr = reinterpret_cast<const ulonglong2*>(xs + b * 128);
        unsigned long long a0 = 0ull, a1 = 0ull;
#pragma unroll
        for (int i = 0; i < 32; i++) {
            const ulonglong2 q = xr[i];     // broadcast LDS.128
            a0 = fma2(q.x, w[2 * i + 0], a0);
            a1 = fma2(q.y, w[2 * i + 1], a1);
        }
        const float s = lo32(a0) + hi32(a0) + lo32(a1) + hi32(a1) + bs;
        out[((size_t)t * B_SZ + (size_t)(b0 + b)) * G_SZ + g] = s;
    }
}

// ---------------------------------------------------------------------------
// Recurrent scan: one CTA per batch element, 384 threads (one per gate output).
// Thread g holds W_hh[g][:] (128 fp32) in registers. Per step:
//   hp[g] = h . W_hh[g] + b_hh[g]   (f32x2 FMA, h via broadcast LDS.128)
//   gates computed by threads 0..127, h updated in smem.
// write_y != 0  -> store h_t to g_y0 each step (layer 0)
// write_y == 0  -> after final step, fused output GEMM h_last @ W_out^T + b_out
// ---------------------------------------------------------------------------
__global__ __launch_bounds__(384, 1)
void recur_kernel(const float* __restrict__ xp,
                  const float* __restrict__ W_hh,
                  const float* __restrict__ b_hh,
                  int write_y,
                  const float* __restrict__ W_out,
                  const float* __restrict__ b_out,
                  float* __restrict__ out)
{
    __shared__ __align__(16) float h_s[H_SZ];
    __shared__ float hp_s[G_SZ];
    __shared__ float xg_s[G_SZ];

    const int b = blockIdx.x;
    const int g = threadIdx.x;

    unsigned long long w[64];
    const unsigned long long* wrow =
        reinterpret_cast<const unsigned long long*>(W_hh + (size_t)g * H_SZ);
#pragma unroll
    for (int i = 0; i < 64; i++) w[i] = wrow[i];
    const float bh = b_hh[g];

    if (g < H_SZ) h_s[g] = 0.0f;

    const float* xptr = xp + (size_t)b * G_SZ + g;
    float xnext = __ldg(xptr);        // prefetch t=0
    __syncthreads();

    for (int t = 0; t < S_LEN; t++) {
        const float xcur = xnext;
        if (t + 1 < S_LEN)
            xnext = __ldg(xptr + (size_t)(t + 1) * B_SZ * G_SZ);  // prefetch next step

        // hp[g] = h . W_hh[g]
        unsigned long long a0 = 0ull, a1 = 0ull;
        const ulonglong2* hq = reinterpret_cast<const ulonglong2*>(h_s);
#pragma unroll
        for (int i = 0; i < 32; i++) {
            const ulonglong2 q = hq[i];   // broadcast LDS.128
            a0 = fma2(q.x, w[2 * i + 0], a0);
            a1 = fma2(q.y, w[2 * i + 1], a1);
        }
        hp_s[g] = lo32(a0) + hi32(a0) + lo32(a1) + hi32(a1) + bh;
        xg_s[g] = xcur;
        __syncthreads();

        if (g < H_SZ) {
            const float pr = xg_s[g]            + hp_s[g];
            const float pz = xg_s[H_SZ + g]     + hp_s[H_SZ + g];
            const float xn = xg_s[2 * H_SZ + g];
            const float hn = hp_s[2 * H_SZ + g];
            const float r = 1.0f / (1.0f + __expf(-pr));
            const float z = 1.0f / (1.0f + __expf(-pz));
            const float n = tanhf(fmaf(r, hn, xn));
            const float hold = h_s[g];
            const float hnew = (1.0f - z) * n + z * hold;
            h_s[g] = hnew;
            if (write_y)
                g_y0[((size_t)t * B_SZ + b) * H_SZ + g] = hnew;
        }
        __syncthreads();
    }

    // Fused final linear layer (layer 1 only): out[b][c] = h_last . W_out[c] + b_out[c]
    if (!write_y && g < C_SZ) {
        float acc = b_out[g];
#pragma unroll 8
        for (int j = 0; j < H_SZ; j++)
            acc = fmaf(h_s[j], W_out[g * H_SZ + j], acc);
        out[b * C_SZ + g] = acc;
    }
}

// ---------------------------------------------------------------------------
// Launch: xp0 GEMM -> layer0 scan -> xp1 GEMM -> layer1 scan (+fused output)
// All on the default stream; graph-capturable (no sync, no alloc).
// ---------------------------------------------------------------------------
extern "C" void kernel_launch(void* const* d_in, const int* in_sizes, int n_in,
                              void* d_out, int out_size)
{
    const float* x     = (const float*)d_in[0];
    const float* W_ih0 = (const float*)d_in[1];
    const float* W_hh0 = (const float*)d_in[2];
    const float* b_ih0 = (const float*)d_in[3];
    const float* b_hh0 = (const float*)d_in[4];
    const float* W_ih1 = (const float*)d_in[5];
    const float* W_hh1 = (const float*)d_in[6];
    const float* b_ih1 = (const float*)d_in[7];
    const float* b_hh1 = (const float*)d_in[8];
    const float* W_out = (const float*)d_in[9];
    const float* b_out = (const float*)d_in[10];
    float* out = (float*)d_out;

    void* xp_ptr = nullptr;
    void* y0_ptr = nullptr;
    cudaGetSymbolAddress(&xp_ptr, g_xp);
    cudaGetSymbolAddress(&y0_ptr, g_y0);
    float* xp = (float*)xp_ptr;
    float* y0 = (float*)y0_ptr;

    const dim3 gemm_grid(S_LEN, 2);

    // Layer 0 input projection: x is [B, S, D] -> strideB = S*D, strideT = D
    gemm_in_kernel<<<gemm_grid, 384>>>(x, W_ih0, b_ih0, xp,
                                       (long)S_LEN * H_SZ, (long)H_SZ);
    // Layer 0 recurrence (writes y0)
    recur_kernel<<<B_SZ, 384>>>(xp, W_hh0, b_hh0, 1, nullptr, nullptr, nullptr);

    // Layer 1 input projection: y0 is [(t*B + b)*H] -> strideB = H, strideT = B*H
    gemm_in_kernel<<<gemm_grid, 384>>>(y0, W_ih1, b_ih1, xp,
                                       (long)H_SZ, (long)B_SZ * H_SZ);
    // Layer 1 recurrence + fused output linear
    recur_kernel<<<B_SZ, 384>>>(xp, W_hh1, b_hh1, 0, W_out, b_out, out);
}